// round 4
// baseline (speedup 1.0000x reference)
#include <cuda_runtime.h>

#define NN 100000
#define EE 1600000
#define SCAN_NB 98   /* ceil(NN/1024) */

// ---------------- scratch (device globals; allocation-free) ----------------
__device__ int   g_deg_out[NN];      // zero-init; re-zeroed by k_scanB each call
__device__ int   g_deg_in[NN];       // zero-init; re-zeroed by k_scanB each call
__device__ int   g_scanS[NN];
__device__ int   g_blocksums[SCAN_NB];
__device__ int   g_rowptr[NN + 1];
__device__ int   g_cursor[NN];
__device__ int   g_csr[EE];
__device__ float g_ns[NN];
__device__ float g_nd[NN];
__device__ float g_hs [NN * 64];
__device__ float g_h2 [2][NN * 64];
__device__ float g_y  [NN * 64];
__device__ float g_red[128];         // zero-init; re-zeroed by colreduce finalize
__device__ int   g_ticket;           // zero-init; reset by colreduce finalize
__device__ float g_mu  [2][64];
__device__ float g_istd[2][64];
__device__ float g_bnA[64];
__device__ float g_bnB[64];

// ---------------- degree histogram ----------------
__global__ void k_hist(const int* __restrict__ src, const int* __restrict__ dst) {
    int i = blockIdx.x * blockDim.x + threadIdx.x;
    if (i < EE) {
        atomicAdd(&g_deg_out[src[i]], 1);
        atomicAdd(&g_deg_in [dst[i]], 1);
    }
}

// ---------------- per-chunk inclusive scan of deg_in ----------------
__global__ void k_scan1() {
    __shared__ int sm[256];
    int base = blockIdx.x * 1024 + threadIdx.x * 4;
    int v[4]; int s = 0;
#pragma unroll
    for (int t = 0; t < 4; t++) {
        v[t] = (base + t < NN) ? g_deg_in[base + t] : 0;
        s += v[t];
    }
    sm[threadIdx.x] = s;
    __syncthreads();
    for (int off = 1; off < 256; off <<= 1) {
        int add = (threadIdx.x >= off) ? sm[threadIdx.x - off] : 0;
        __syncthreads();
        sm[threadIdx.x] += add;
        __syncthreads();
    }
    int run = sm[threadIdx.x] - s;   // exclusive prefix for this thread
#pragma unroll
    for (int t = 0; t < 4; t++) {
        run += v[t];
        if (base + t < NN) g_scanS[base + t] = run;   // inclusive within chunk
    }
    if (threadIdx.x == 255) g_blocksums[blockIdx.x] = sm[255];
}

// ------- fused: chunk-offset + rowptr/cursor + norms + degree re-zero -------
__global__ void __launch_bounds__(256) k_scanB() {
    __shared__ int sred[256];
    int t = threadIdx.x;
    int cb = (blockIdx.x * 256) >> 10;            // this block's 1024-chunk index
    sred[t] = (t < cb) ? g_blocksums[t] : 0;      // cb <= 97 < SCAN_NB
    __syncthreads();
#pragma unroll
    for (int off = 128; off > 0; off >>= 1) {
        if (t < off) sred[t] += sred[t + off];
        __syncthreads();
    }
    int offset = sred[0];
    int i = blockIdx.x * 256 + t;
    if (i < NN) {
        int din  = g_deg_in[i];
        int dout = g_deg_out[i];
        int incl = g_scanS[i] + offset;
        int excl = incl - din;
        g_rowptr[i] = excl;
        g_cursor[i] = excl;
        if (i == NN - 1) g_rowptr[NN] = incl;
        float fo = (dout < 1) ? 1.f : (float)dout;
        float fi = (din  < 1) ? 1.f : (float)din;
        g_ns[i] = rsqrtf(fo);
        g_nd[i] = rsqrtf(fi);
        g_deg_out[i] = 0;
        g_deg_in [i] = 0;
    }
}

// ---------------- CSR scatter (counting sort by dst) ----------------
__global__ void k_scatter(const int* __restrict__ src, const int* __restrict__ dst) {
    int i = blockIdx.x * blockDim.x + threadIdx.x;
    if (i < EE) {
        int d = dst[i];
        int p = atomicAdd(&g_cursor[d], 1);
        g_csr[p] = src[i];
    }
}

// ------- fused SpMM + GEMM: out = act( (nd * sum_{e} ns?*x[src]) @ W + b ) [*ns] -------
// 16 lanes per dst node; lane c holds cols 4c..4c+3. Epilogue via width-16 shuffles.
__global__ void __launch_bounds__(512) k_fused(const float* __restrict__ feat,
                                               const float* __restrict__ W,
                                               const float* __restrict__ bias,
                                               int out_sel, int layer1) {
    __shared__ float4 sW4[1024];   // 64x64 row-major, row stride 16 float4
    int tid = threadIdx.x;
#pragma unroll
    for (int i = tid; i < 1024; i += 512) sW4[i] = ((const float4*)W)[i];
    __syncthreads();

    const float* __restrict__ xin = layer1 ? feat : g_hs;
    float* __restrict__ out = (out_sel == 0) ? g_hs : ((out_sel == 1) ? g_h2[0] : g_h2[1]);

    int t = blockIdx.x * 512 + tid;        // grid is exactly NN*16 threads
    int node = t >> 4, c = t & 15;
    int s0 = g_rowptr[node], s1 = g_rowptr[node + 1];
    int deg = s1 - s0;
    float4 accA = make_float4(0.f, 0.f, 0.f, 0.f);
    float4 accB = make_float4(0.f, 0.f, 0.f, 0.f);
    int j = s0;
    if (layer1) {
        for (int it = deg >> 1; it > 0; it--, j += 2) {
            int sA = __ldg(&g_csr[j]);
            int sB = __ldg(&g_csr[j + 1]);
            float nsA = __ldg(&g_ns[sA]);
            float nsB = __ldg(&g_ns[sB]);
            float4 vA = *(const float4*)(xin + sA * 64 + c * 4);
            float4 vB = *(const float4*)(xin + sB * 64 + c * 4);
            accA.x = fmaf(vA.x, nsA, accA.x); accA.y = fmaf(vA.y, nsA, accA.y);
            accA.z = fmaf(vA.z, nsA, accA.z); accA.w = fmaf(vA.w, nsA, accA.w);
            accB.x = fmaf(vB.x, nsB, accB.x); accB.y = fmaf(vB.y, nsB, accB.y);
            accB.z = fmaf(vB.z, nsB, accB.z); accB.w = fmaf(vB.w, nsB, accB.w);
        }
        if (deg & 1) {
            int sA = __ldg(&g_csr[j]);
            float nsA = __ldg(&g_ns[sA]);
            float4 vA = *(const float4*)(xin + sA * 64 + c * 4);
            accA.x = fmaf(vA.x, nsA, accA.x); accA.y = fmaf(vA.y, nsA, accA.y);
            accA.z = fmaf(vA.z, nsA, accA.z); accA.w = fmaf(vA.w, nsA, accA.w);
        }
    } else {
        for (int it = deg >> 1; it > 0; it--, j += 2) {
            int sA = __ldg(&g_csr[j]);
            int sB = __ldg(&g_csr[j + 1]);
            float4 vA = *(const float4*)(xin + sA * 64 + c * 4);
            float4 vB = *(const float4*)(xin + sB * 64 + c * 4);
            accA.x += vA.x; accA.y += vA.y; accA.z += vA.z; accA.w += vA.w;
            accB.x += vB.x; accB.y += vB.y; accB.z += vB.z; accB.w += vB.w;
        }
        if (deg & 1) {
            int sA = __ldg(&g_csr[j]);
            float4 vA = *(const float4*)(xin + sA * 64 + c * 4);
            accA.x += vA.x; accA.y += vA.y; accA.z += vA.z; accA.w += vA.w;
        }
    }
    float nd = g_nd[node];
    accA.x = (accA.x + accB.x) * nd;
    accA.y = (accA.y + accB.y) * nd;
    accA.z = (accA.z + accB.z) * nd;
    accA.w = (accA.w + accB.w) * nd;

    // epilogue: o[4c..4c+3] = a @ W + b  via width-16 broadcast of a
    float4 o = ((const float4*)bias)[c];
#pragma unroll
    for (int kk = 0; kk < 16; kk++) {
        float a0 = __shfl_sync(0xffffffffu, accA.x, kk, 16);
        float a1 = __shfl_sync(0xffffffffu, accA.y, kk, 16);
        float a2 = __shfl_sync(0xffffffffu, accA.z, kk, 16);
        float a3 = __shfl_sync(0xffffffffu, accA.w, kk, 16);
        float4 w0 = sW4[(kk * 4 + 0) * 16 + c];
        float4 w1 = sW4[(kk * 4 + 1) * 16 + c];
        float4 w2 = sW4[(kk * 4 + 2) * 16 + c];
        float4 w3 = sW4[(kk * 4 + 3) * 16 + c];
        o.x = fmaf(a0, w0.x, fmaf(a1, w1.x, fmaf(a2, w2.x, fmaf(a3, w3.x, o.x))));
        o.y = fmaf(a0, w0.y, fmaf(a1, w1.y, fmaf(a2, w2.y, fmaf(a3, w3.y, o.y))));
        o.z = fmaf(a0, w0.z, fmaf(a1, w1.z, fmaf(a2, w2.z, fmaf(a3, w3.z, o.z))));
        o.w = fmaf(a0, w0.w, fmaf(a1, w1.w, fmaf(a2, w2.w, fmaf(a3, w3.w, o.w))));
    }
    if (layer1) {
        float s = g_ns[node];
        o.x = fmaxf(o.x, 0.f) * s; o.y = fmaxf(o.y, 0.f) * s;
        o.z = fmaxf(o.z, 0.f) * s; o.w = fmaxf(o.w, 0.f) * s;
    }
    ((float4*)out)[node * 16 + c] = o;
}

// ------- column sum/sumsq reduce, fused finalize via last-block ticket -------
// mode 0: z-score stats (ddof=1) into g_mu[g]/g_istd[g]; mode 1: BN coeffs.
__global__ void __launch_bounds__(256) k_colreduce(int which, int mode, int g,
                                                   const float* __restrict__ gamma,
                                                   const float* __restrict__ beta) {
    const float* __restrict__ buf = (which == 0) ? g_h2[0] : ((which == 1) ? g_h2[1] : g_y);
    __shared__ float ss[256], sq[256];
    __shared__ bool is_last;
    int col = threadIdx.x & 63;
    int rg = threadIdx.x >> 6;
    float s = 0.f, q = 0.f;
    for (int r = blockIdx.x * 4 + rg; r < NN; r += gridDim.x * 4) {
        float v = buf[r * 64 + col];
        s += v; q += v * v;
    }
    ss[threadIdx.x] = s; sq[threadIdx.x] = q;
    __syncthreads();
    if (threadIdx.x < 128) {
        ss[threadIdx.x] += ss[threadIdx.x + 128];
        sq[threadIdx.x] += sq[threadIdx.x + 128];
    }
    __syncthreads();
    if (threadIdx.x < 64) {
        atomicAdd(&g_red[col],      ss[threadIdx.x] + ss[threadIdx.x + 64]);
        atomicAdd(&g_red[64 + col], sq[threadIdx.x] + sq[threadIdx.x + 64]);
    }
    __threadfence();
    if (threadIdx.x == 0) {
        int tk = atomicAdd(&g_ticket, 1);
        is_last = (tk == (int)gridDim.x - 1);
    }
    __syncthreads();
    if (is_last) {
        if (threadIdx.x < 64) {
            int c = threadIdx.x;
            float S = g_red[c], Q = g_red[64 + c];
            g_red[c] = 0.f; g_red[64 + c] = 0.f;
            float mu = S / (float)NN;
            if (mode == 0) {
                float var = (Q - (float)NN * mu * mu) / (float)(NN - 1);
                g_mu[g][c] = mu;
                g_istd[g][c] = rsqrtf(var);
            } else {
                float var = Q / (float)NN - mu * mu;
                float sc = gamma[c] * rsqrtf(var + 1e-5f);
                g_bnA[c] = sc;
                g_bnB[c] = beta[c] - mu * sc;
            }
        }
        if (threadIdx.x == 0) g_ticket = 0;
    }
}

// ---------------- z1/z2 write + z = avg + y = z @ Wm1 + bm1 ----------------
__global__ void __launch_bounds__(128) k_zy(const float* __restrict__ Wm1,
                                            const float* __restrict__ bm1,
                                            float* __restrict__ out) {
    __shared__ float sW[64 * 64];
    __shared__ float sa[16][65];
    int tid = threadIdx.x;
    for (int idx = tid; idx < 1024; idx += 128)
        ((float4*)sW)[idx] = ((const float4*)Wm1)[idx];
    int cg = tid & 15, ng = tid >> 4;
    float4 b4 = ((const float4*)bm1)[cg];
    int blockbase = blockIdx.x * 64;
    for (int ch = 0; ch < 4; ch++) {
        int cb = blockbase + ch * 16;
        __syncthreads();
        for (int idx = tid; idx < 1024; idx += 128) {
            int n = idx >> 6, k = idx & 63;
            int gn = cb + n;
            float v = 0.f;
            if (gn < NN) {
                float z1 = (g_h2[0][gn * 64 + k] - g_mu[0][k]) * g_istd[0][k];
                float z2 = (g_h2[1][gn * 64 + k] - g_mu[1][k]) * g_istd[1][k];
                out[gn * 64 + k] = z1;
                out[NN * 64 + gn * 64 + k] = z2;
                v = 0.5f * (z1 + z2);
            }
            sa[n][k] = v;
        }
        __syncthreads();
        float4 A0 = make_float4(0.f, 0.f, 0.f, 0.f);
        float4 A1 = make_float4(0.f, 0.f, 0.f, 0.f);
#pragma unroll
        for (int k = 0; k < 64; k++) {
            float4 w = *(const float4*)&sW[k * 64 + cg * 4];
            float a0 = sa[ng * 2][k];
            float a1 = sa[ng * 2 + 1][k];
            A0.x = fmaf(a0, w.x, A0.x); A0.y = fmaf(a0, w.y, A0.y);
            A0.z = fmaf(a0, w.z, A0.z); A0.w = fmaf(a0, w.w, A0.w);
            A1.x = fmaf(a1, w.x, A1.x); A1.y = fmaf(a1, w.y, A1.y);
            A1.z = fmaf(a1, w.z, A1.z); A1.w = fmaf(a1, w.w, A1.w);
        }
        int gn0 = cb + ng * 2, gn1 = gn0 + 1;
        A0.x += b4.x; A0.y += b4.y; A0.z += b4.z; A0.w += b4.w;
        A1.x += b4.x; A1.y += b4.y; A1.z += b4.z; A1.w += b4.w;
        if (gn0 < NN) ((float4*)g_y)[gn0 * 16 + cg] = A0;
        if (gn1 < NN) ((float4*)g_y)[gn1 * 16 + cg] = A1;
    }
}

// ---------------- head: relu(BN(y)) @ Wm2 + bm2 ----------------
__global__ void __launch_bounds__(192) k_head(const float* __restrict__ W2,
                                              const float* __restrict__ b2,
                                              float* __restrict__ out) {
    __shared__ float sW2[64 * 48];
    __shared__ float st[32][65];
    __shared__ float sb[48];
    int tid = threadIdx.x;
    for (int idx = tid; idx < 64 * 12; idx += 192) {
        int k = idx / 12, c = idx % 12;
        float4 v = make_float4(0.f, 0.f, 0.f, 0.f);
        if (c < 10) v = *(const float4*)&W2[k * 40 + c * 4];
        ((float4*)sW2)[k * 12 + c] = v;
    }
    if (tid < 48) sb[tid] = (tid < 40) ? b2[tid] : 0.f;
    int cg = tid % 12, ng = tid / 12;
    int blockbase = blockIdx.x * 64;
    for (int ch = 0; ch < 2; ch++) {
        int cb = blockbase + ch * 32;
        __syncthreads();
        for (int idx = tid; idx < 2048; idx += 192) {
            int n = idx >> 6, k = idx & 63;
            int gn = cb + n;
            float v = 0.f;
            if (gn < NN) {
                v = g_y[gn * 64 + k] * g_bnA[k] + g_bnB[k];
                v = fmaxf(v, 0.f);
            }
            st[n][k] = v;
        }
        __syncthreads();
        float4 A0 = make_float4(0.f, 0.f, 0.f, 0.f);
        float4 A1 = make_float4(0.f, 0.f, 0.f, 0.f);
#pragma unroll
        for (int k = 0; k < 64; k++) {
            float4 w = ((float4*)sW2)[k * 12 + cg];
            float a0 = st[ng * 2][k];
            float a1 = st[ng * 2 + 1][k];
            A0.x = fmaf(a0, w.x, A0.x); A0.y = fmaf(a0, w.y, A0.y);
            A0.z = fmaf(a0, w.z, A0.z); A0.w = fmaf(a0, w.w, A0.w);
            A1.x = fmaf(a1, w.x, A1.x); A1.y = fmaf(a1, w.y, A1.y);
            A1.z = fmaf(a1, w.z, A1.z); A1.w = fmaf(a1, w.w, A1.w);
        }
        int gn0 = cb + ng * 2, gn1 = gn0 + 1;
        float r0[4] = {A0.x + sb[cg * 4], A0.y + sb[cg * 4 + 1], A0.z + sb[cg * 4 + 2], A0.w + sb[cg * 4 + 3]};
        float r1[4] = {A1.x + sb[cg * 4], A1.y + sb[cg * 4 + 1], A1.z + sb[cg * 4 + 2], A1.w + sb[cg * 4 + 3]};
        float* pred = out + (size_t)NN * 128;
#pragma unroll
        for (int i = 0; i < 4; i++) {
            int col = cg * 4 + i;
            if (col < 40) {
                if (gn0 < NN) pred[gn0 * 40 + col] = r0[i];
                if (gn1 < NN) pred[gn1 * 40 + col] = r1[i];
            }
        }
    }
}

// ---------------- launch ----------------
extern "C" void kernel_launch(void* const* d_in, const int* in_sizes, int n_in,
                              void* d_out, int out_size) {
    const float* feat[2] = {(const float*)d_in[0], (const float*)d_in[3]};
    const int*   src [2] = {(const int*)d_in[1], (const int*)d_in[4]};
    const int*   dst [2] = {(const int*)d_in[2], (const int*)d_in[5]};
    const float* W1  [2] = {(const float*)d_in[6],  (const float*)d_in[10]};
    const float* B1  [2] = {(const float*)d_in[7],  (const float*)d_in[11]};
    const float* W2  [2] = {(const float*)d_in[8],  (const float*)d_in[12]};
    const float* B2  [2] = {(const float*)d_in[9],  (const float*)d_in[13]};
    const float* Wm1   = (const float*)d_in[14];
    const float* bm1   = (const float*)d_in[15];
    const float* gamma = (const float*)d_in[16];
    const float* beta  = (const float*)d_in[17];
    const float* Wm2   = (const float*)d_in[18];
    const float* bm2   = (const float*)d_in[19];
    float* out = (float*)d_out;

    const int EB = (EE + 255) / 256;        // 6250
    const int NB = (NN + 255) / 256;        // 391
    const int FB = (NN * 16) / 512;         // 3125 (exact)
    const int GB = (NN + 63) / 64;          // 1563

    for (int g = 0; g < 2; g++) {
        k_hist<<<EB, 256>>>(src[g], dst[g]);
        k_scan1<<<SCAN_NB, 256>>>();
        k_scanB<<<NB, 256>>>();
        k_scatter<<<EB, 256>>>(src[g], dst[g]);
        k_fused<<<FB, 512>>>(feat[g], W1[g], B1[g], 0, 1);
        k_fused<<<FB, 512>>>(feat[g], W2[g], B2[g], 1 + g, 0);
        k_colreduce<<<512, 256>>>(g, 0, g, gamma, beta);
    }
    k_zy<<<GB, 128>>>(Wm1, bm1, out);
    k_colreduce<<<512, 256>>>(2, 1, 0, gamma, beta);
    k_head<<<GB, 192>>>(Wm2, bm2, out);
}

// round 6
// speedup vs baseline: 1.1667x; 1.1667x over previous
#include <cuda_runtime.h>
#include <cuda_fp16.h>

#define NN 100000
#define EE 1600000
#define SCAN_NB 98   /* ceil(NN/1024) */

// ---------------- scratch (device globals; allocation-free) ----------------
__device__ int   g_deg_out[2][NN];   // zero-init; re-zeroed by k_scanB each call
__device__ int   g_deg_in [2][NN];   // zero-init; re-zeroed by k_scanB each call
__device__ int   g_scanS[2][NN];
__device__ int   g_blocksums[2][SCAN_NB];
__device__ int   g_rowptr[2][NN + 1];
__device__ int   g_cursor[2][NN];
__device__ int   g_csr[2][EE];
__device__ float g_ns[2][NN];
__device__ float g_nd[2][NN];
__device__ uint4 g_xh [2][NN * 8];   // half feature table (64 halfs/row = 128B)
__device__ uint2 g_hsh[2][NN * 16];  // half hidden table
__device__ float g_agg[2][NN * 64];
__device__ float g_h2 [2][NN * 64];
__device__ float g_y  [NN * 64];
__device__ float g_red[2][128];      // zero-init; re-zeroed by colreduce finalize
__device__ int   g_ticket[2];        // zero-init; reset by colreduce finalize
__device__ float g_mu  [2][64];
__device__ float g_istd[2][64];
__device__ float g_bnA[64];
__device__ float g_bnB[64];

__device__ __forceinline__ unsigned packh2(float a, float b) {
    __half2 h = __floats2half2_rn(a, b);
    return *reinterpret_cast<unsigned*>(&h);
}
__device__ __forceinline__ float2 unpackh2(unsigned u) {
    __half2 h = *reinterpret_cast<__half2*>(&u);
    return __half22float2(h);
}

// ---------------- degree histogram (both graphs) ----------------
__global__ void k_hist(const int* __restrict__ s0, const int* __restrict__ d0,
                       const int* __restrict__ s1, const int* __restrict__ d1) {
    int g = blockIdx.y;
    const int* __restrict__ src = g ? s1 : s0;
    const int* __restrict__ dst = g ? d1 : d0;
    int i = blockIdx.x * blockDim.x + threadIdx.x;
    if (i < EE) {
        atomicAdd(&g_deg_out[g][src[i]], 1);
        atomicAdd(&g_deg_in [g][dst[i]], 1);
    }
}

// ---------------- per-chunk inclusive scan of deg_in ----------------
__global__ void k_scan1() {
    int g = blockIdx.y;
    __shared__ int sm[256];
    int base = blockIdx.x * 1024 + threadIdx.x * 4;
    int v[4]; int s = 0;
#pragma unroll
    for (int t = 0; t < 4; t++) {
        v[t] = (base + t < NN) ? g_deg_in[g][base + t] : 0;
        s += v[t];
    }
    sm[threadIdx.x] = s;
    __syncthreads();
    for (int off = 1; off < 256; off <<= 1) {
        int add = (threadIdx.x >= off) ? sm[threadIdx.x - off] : 0;
        __syncthreads();
        sm[threadIdx.x] += add;
        __syncthreads();
    }
    int run = sm[threadIdx.x] - s;
#pragma unroll
    for (int t = 0; t < 4; t++) {
        run += v[t];
        if (base + t < NN) g_scanS[g][base + t] = run;
    }
    if (threadIdx.x == 255) g_blocksums[g][blockIdx.x] = sm[255];
}

// ------- fused: chunk-offset + rowptr/cursor + norms + degree re-zero -------
__global__ void __launch_bounds__(256) k_scanB() {
    int g = blockIdx.y;
    __shared__ int sred[256];
    int t = threadIdx.x;
    int cb = (blockIdx.x * 256) >> 10;
    sred[t] = (t < cb) ? g_blocksums[g][t] : 0;
    __syncthreads();
#pragma unroll
    for (int off = 128; off > 0; off >>= 1) {
        if (t < off) sred[t] += sred[t + off];
        __syncthreads();
    }
    int offset = sred[0];
    int i = blockIdx.x * 256 + t;
    if (i < NN) {
        int din  = g_deg_in[g][i];
        int dout = g_deg_out[g][i];
        int incl = g_scanS[g][i] + offset;
        int excl = incl - din;
        g_rowptr[g][i] = excl;
        g_cursor[g][i] = excl;
        if (i == NN - 1) g_rowptr[g][NN] = incl;
        float fo = (dout < 1) ? 1.f : (float)dout;
        float fi = (din  < 1) ? 1.f : (float)din;
        g_ns[g][i] = rsqrtf(fo);
        g_nd[g][i] = rsqrtf(fi);
        g_deg_out[g][i] = 0;
        g_deg_in [g][i] = 0;
    }
}

// ---------------- CSR scatter (counting sort by dst) ----------------
__global__ void k_scatter(const int* __restrict__ s0, const int* __restrict__ d0,
                          const int* __restrict__ s1, const int* __restrict__ d1) {
    int g = blockIdx.y;
    const int* __restrict__ src = g ? s1 : s0;
    const int* __restrict__ dst = g ? d1 : d0;
    int i = blockIdx.x * blockDim.x + threadIdx.x;
    if (i < EE) {
        int d = dst[i];
        int p = atomicAdd(&g_cursor[g][d], 1);
        g_csr[g][p] = src[i];
    }
}

// ---------------- xh = half(feat * ns) ----------------
__global__ void __launch_bounds__(256) k_scalefeat(const float* __restrict__ f0,
                                                   const float* __restrict__ f1) {
    int g = blockIdx.y;
    const float* __restrict__ feat = g ? f1 : f0;
    int idx = blockIdx.x * 256 + threadIdx.x;   // [0, NN*8)
    int node = idx >> 3, c = idx & 7;
    float s = g_ns[g][node];
    float4 v0 = ((const float4*)feat)[node * 16 + c * 2];
    float4 v1 = ((const float4*)feat)[node * 16 + c * 2 + 1];
    uint4 o;
    o.x = packh2(v0.x * s, v0.y * s);
    o.y = packh2(v0.z * s, v0.w * s);
    o.z = packh2(v1.x * s, v1.y * s);
    o.w = packh2(v1.z * s, v1.w * s);
    g_xh[g][idx] = o;
}

// ------- gather SpMM (half rows, fp32 accum): agg[d] = nd * sum xsrc[s] -------
// 8 lanes per dst node; lane c holds cols 8c..8c+7 (one uint4 = 8 halfs).
__global__ void __launch_bounds__(256) k_spmm(int lay) {
    int g = blockIdx.y;
    const uint4* __restrict__ table = lay ? (const uint4*)g_hsh[g] : g_xh[g];
    int t = blockIdx.x * 256 + threadIdx.x;     // [0, NN*8)
    int node = t >> 3, c = t & 7;
    int s0 = g_rowptr[g][node], s1 = g_rowptr[g][node + 1];
    int deg = s1 - s0;
    const int* __restrict__ csr = g_csr[g];
    float2 a0 = {0.f,0.f}, a1 = {0.f,0.f}, a2 = {0.f,0.f}, a3 = {0.f,0.f};
    float2 b0 = {0.f,0.f}, b1 = {0.f,0.f}, b2 = {0.f,0.f}, b3 = {0.f,0.f};
    int j = s0;
    for (int it = deg >> 1; it > 0; it--, j += 2) {
        int sA = __ldg(&csr[j]);
        int sB = __ldg(&csr[j + 1]);
        uint4 vA = __ldg(&table[sA * 8 + c]);
        uint4 vB = __ldg(&table[sB * 8 + c]);
        float2 f;
        f = unpackh2(vA.x); a0.x += f.x; a0.y += f.y;
        f = unpackh2(vA.y); a1.x += f.x; a1.y += f.y;
        f = unpackh2(vA.z); a2.x += f.x; a2.y += f.y;
        f = unpackh2(vA.w); a3.x += f.x; a3.y += f.y;
        f = unpackh2(vB.x); b0.x += f.x; b0.y += f.y;
        f = unpackh2(vB.y); b1.x += f.x; b1.y += f.y;
        f = unpackh2(vB.z); b2.x += f.x; b2.y += f.y;
        f = unpackh2(vB.w); b3.x += f.x; b3.y += f.y;
    }
    if (deg & 1) {
        int sA = __ldg(&csr[j]);
        uint4 vA = __ldg(&table[sA * 8 + c]);
        float2 f;
        f = unpackh2(vA.x); a0.x += f.x; a0.y += f.y;
        f = unpackh2(vA.y); a1.x += f.x; a1.y += f.y;
        f = unpackh2(vA.z); a2.x += f.x; a2.y += f.y;
        f = unpackh2(vA.w); a3.x += f.x; a3.y += f.y;
    }
    float nd = g_nd[g][node];
    float4 o0, o1;
    o0.x = (a0.x + b0.x) * nd; o0.y = (a0.y + b0.y) * nd;
    o0.z = (a1.x + b1.x) * nd; o0.w = (a1.y + b1.y) * nd;
    o1.x = (a2.x + b2.x) * nd; o1.y = (a2.y + b2.y) * nd;
    o1.z = (a3.x + b3.x) * nd; o1.w = (a3.y + b3.y) * nd;
    ((float4*)&g_agg[g][node * 64])[c * 2]     = o0;
    ((float4*)&g_agg[g][node * 64])[c * 2 + 1] = o1;
}

// ------- node GEMM: out = act(agg @ W + b); layer1 -> half table, layer2 -> fp32 -------
__global__ void __launch_bounds__(128) k_gemm(const float* __restrict__ Wa,
                                              const float* __restrict__ ba,
                                              const float* __restrict__ Wb,
                                              const float* __restrict__ bb,
                                              int layer1) {
    int g = blockIdx.y;
    const float* __restrict__ W    = g ? Wb : Wa;
    const float* __restrict__ bias = g ? bb : ba;
    __shared__ float sW[64 * 64];
    __shared__ float sa[16][65];
    int tid = threadIdx.x;
    for (int idx = tid; idx < 1024; idx += 128)
        ((float4*)sW)[idx] = ((const float4*)W)[idx];
    int cg = tid & 15, ng = tid >> 4;
    float4 b4 = ((const float4*)bias)[cg];
    int blockbase = blockIdx.x * 64;
    for (int ch = 0; ch < 4; ch++) {
        int cb = blockbase + ch * 16;
        __syncthreads();
        for (int idx = tid; idx < 1024; idx += 128) {
            int n = idx >> 6, k = idx & 63;
            int gn = cb + n;
            sa[n][k] = (gn < NN) ? g_agg[g][gn * 64 + k] : 0.f;
        }
        __syncthreads();
        float4 A0 = make_float4(0.f, 0.f, 0.f, 0.f);
        float4 A1 = make_float4(0.f, 0.f, 0.f, 0.f);
#pragma unroll
        for (int k = 0; k < 64; k++) {
            float4 w = *(const float4*)&sW[k * 64 + cg * 4];
            float a0 = sa[ng * 2][k];
            float a1 = sa[ng * 2 + 1][k];
            A0.x = fmaf(a0, w.x, A0.x); A0.y = fmaf(a0, w.y, A0.y);
            A0.z = fmaf(a0, w.z, A0.z); A0.w = fmaf(a0, w.w, A0.w);
            A1.x = fmaf(a1, w.x, A1.x); A1.y = fmaf(a1, w.y, A1.y);
            A1.z = fmaf(a1, w.z, A1.z); A1.w = fmaf(a1, w.w, A1.w);
        }
        int gn0 = cb + ng * 2, gn1 = gn0 + 1;
        A0.x += b4.x; A0.y += b4.y; A0.z += b4.z; A0.w += b4.w;
        A1.x += b4.x; A1.y += b4.y; A1.z += b4.z; A1.w += b4.w;
        if (layer1) {
            if (gn0 < NN) {
                float s = g_ns[g][gn0];
                float x0 = fmaxf(A0.x, 0.f) * s, x1 = fmaxf(A0.y, 0.f) * s;
                float x2 = fmaxf(A0.z, 0.f) * s, x3 = fmaxf(A0.w, 0.f) * s;
                uint2 u; u.x = packh2(x0, x1); u.y = packh2(x2, x3);
                g_hsh[g][gn0 * 16 + cg] = u;
            }
            if (gn1 < NN) {
                float s = g_ns[g][gn1];
                float x0 = fmaxf(A1.x, 0.f) * s, x1 = fmaxf(A1.y, 0.f) * s;
                float x2 = fmaxf(A1.z, 0.f) * s, x3 = fmaxf(A1.w, 0.f) * s;
                uint2 u; u.x = packh2(x0, x1); u.y = packh2(x2, x3);
                g_hsh[g][gn1 * 16 + cg] = u;
            }
        } else {
            if (gn0 < NN) ((float4*)&g_h2[g][0])[gn0 * 16 + cg] = A0;
            if (gn1 < NN) ((float4*)&g_h2[g][0])[gn1 * 16 + cg] = A1;
        }
    }
}

// ------- column sum/sumsq reduce + fused finalize (last-block ticket) -------
// mode 0: z-stats (ddof=1) for g_h2[blockIdx.y]; mode 1: BN coeffs for g_y.
__global__ void __launch_bounds__(256) k_colreduce(int mode,
                                                   const float* __restrict__ gamma,
                                                   const float* __restrict__ beta) {
    int g = blockIdx.y;
    const float* __restrict__ buf = (mode == 0) ? g_h2[g] : g_y;
    __shared__ float ss[256], sq[256];
    __shared__ bool is_last;
    int col = threadIdx.x & 63;
    int rg = threadIdx.x >> 6;
    float s = 0.f, q = 0.f;
    for (int r = blockIdx.x * 4 + rg; r < NN; r += gridDim.x * 4) {
        float v = buf[r * 64 + col];
        s += v; q = fmaf(v, v, q);
    }
    ss[threadIdx.x] = s; sq[threadIdx.x] = q;
    __syncthreads();
    if (threadIdx.x < 128) {
        ss[threadIdx.x] += ss[threadIdx.x + 128];
        sq[threadIdx.x] += sq[threadIdx.x + 128];
    }
    __syncthreads();
    if (threadIdx.x < 64) {
        atomicAdd(&g_red[g][col],      ss[threadIdx.x] + ss[threadIdx.x + 64]);
        atomicAdd(&g_red[g][64 + col], sq[threadIdx.x] + sq[threadIdx.x + 64]);
    }
    __threadfence();
    if (threadIdx.x == 0) {
        int tk = atomicAdd(&g_ticket[g], 1);
        is_last = (tk == (int)gridDim.x - 1);
    }
    __syncthreads();
    if (is_last) {
        if (threadIdx.x < 64) {
            int c = threadIdx.x;
            float S = g_red[g][c], Q = g_red[g][64 + c];
            g_red[g][c] = 0.f; g_red[g][64 + c] = 0.f;
            float mu = S / (float)NN;
            if (mode == 0) {
                float var = (Q - (float)NN * mu * mu) / (float)(NN - 1);
                g_mu[g][c] = mu;
                g_istd[g][c] = rsqrtf(var);
            } else {
                float var = Q / (float)NN - mu * mu;
                float sc = gamma[c] * rsqrtf(var + 1e-5f);
                g_bnA[c] = sc;
                g_bnB[c] = beta[c] - mu * sc;
            }
        }
        if (threadIdx.x == 0) g_ticket[g] = 0;
    }
}

// ---------------- z1/z2 write + z = avg + y = z @ Wm1 + bm1 ----------------
__global__ void __launch_bounds__(128) k_zy(const float* __restrict__ Wm1,
                                            const float* __restrict__ bm1,
                                            float* __restrict__ out) {
    __shared__ float sW[64 * 64];
    __shared__ float sa[16][65];
    int tid = threadIdx.x;
    for (int idx = tid; idx < 1024; idx += 128)
        ((float4*)sW)[idx] = ((const float4*)Wm1)[idx];
    int cg = tid & 15, ng = tid >> 4;
    float4 b4 = ((const float4*)bm1)[cg];
    int blockbase = blockIdx.x * 64;
    for (int ch = 0; ch < 4; ch++) {
        int cb = blockbase + ch * 16;
        __syncthreads();
        for (int idx = tid; idx < 1024; idx += 128) {
            int n = idx >> 6, k = idx & 63;
            int gn = cb + n;
            float v = 0.f;
            if (gn < NN) {
                float z1 = (g_h2[0][gn * 64 + k] - g_mu[0][k]) * g_istd[0][k];
                float z2 = (g_h2[1][gn * 64 + k] - g_mu[1][k]) * g_istd[1][k];
                out[gn * 64 + k] = z1;
                out[NN * 64 + gn * 64 + k] = z2;
                v = 0.5f * (z1 + z2);
            }
            sa[n][k] = v;
        }
        __syncthreads();
        float4 A0 = make_float4(0.f, 0.f, 0.f, 0.f);
        float4 A1 = make_float4(0.f, 0.f, 0.f, 0.f);
#pragma unroll
        for (int k = 0; k < 64; k++) {
            float4 w = *(const float4*)&sW[k * 64 + cg * 4];
            float a0 = sa[ng * 2][k];
            float a1 = sa[ng * 2 + 1][k];
            A0.x = fmaf(a0, w.x, A0.x); A0.y = fmaf(a0, w.y, A0.y);
            A0.z = fmaf(a0, w.z, A0.z); A0.w = fmaf(a0, w.w, A0.w);
            A1.x = fmaf(a1, w.x, A1.x); A1.y = fmaf(a1, w.y, A1.y);
            A1.z = fmaf(a1, w.z, A1.z); A1.w = fmaf(a1, w.w, A1.w);
        }
        int gn0 = cb + ng * 2, gn1 = gn0 + 1;
        A0.x += b4.x; A0.y += b4.y; A0.z += b4.z; A0.w += b4.w;
        A1.x += b4.x; A1.y += b4.y; A1.z += b4.z; A1.w += b4.w;
        if (gn0 < NN) ((float4*)g_y)[gn0 * 16 + cg] = A0;
        if (gn1 < NN) ((float4*)g_y)[gn1 * 16 + cg] = A1;
    }
}

// ---------------- head: relu(BN(y)) @ Wm2 + bm2 ----------------
__global__ void __launch_bounds__(192) k_head(const float* __restrict__ W2,
                                              const float* __restrict__ b2,
                                              float* __restrict__ out) {
    __shared__ float sW2[64 * 48];
    __shared__ float st[32][65];
    __shared__ float sb[48];
    int tid = threadIdx.x;
    for (int idx = tid; idx < 64 * 12; idx += 192) {
        int k = idx / 12, c = idx % 12;
        float4 v = make_float4(0.f, 0.f, 0.f, 0.f);
        if (c < 10) v = *(const float4*)&W2[k * 40 + c * 4];
        ((float4*)sW2)[k * 12 + c] = v;
    }
    if (tid < 48) sb[tid] = (tid < 40) ? b2[tid] : 0.f;
    int cg = tid % 12, ng = tid / 12;
    int blockbase = blockIdx.x * 64;
    for (int ch = 0; ch < 2; ch++) {
        int cb = blockbase + ch * 32;
        __syncthreads();
        for (int idx = tid; idx < 2048; idx += 192) {
            int n = idx >> 6, k = idx & 63;
            int gn = cb + n;
            float v = 0.f;
            if (gn < NN) {
                v = g_y[gn * 64 + k] * g_bnA[k] + g_bnB[k];
                v = fmaxf(v, 0.f);
            }
            st[n][k] = v;
        }
        __syncthreads();
        float4 A0 = make_float4(0.f, 0.f, 0.f, 0.f);
        float4 A1 = make_float4(0.f, 0.f, 0.f, 0.f);
#pragma unroll
        for (int k = 0; k < 64; k++) {
            float4 w = ((float4*)sW2)[k * 12 + cg];
            float a0 = st[ng * 2][k];
            float a1 = st[ng * 2 + 1][k];
            A0.x = fmaf(a0, w.x, A0.x); A0.y = fmaf(a0, w.y, A0.y);
            A0.z = fmaf(a0, w.z, A0.z); A0.w = fmaf(a0, w.w, A0.w);
            A1.x = fmaf(a1, w.x, A1.x); A1.y = fmaf(a1, w.y, A1.y);
            A1.z = fmaf(a1, w.z, A1.z); A1.w = fmaf(a1, w.w, A1.w);
        }
        int gn0 = cb + ng * 2, gn1 = gn0 + 1;
        float r0[4] = {A0.x + sb[cg * 4], A0.y + sb[cg * 4 + 1], A0.z + sb[cg * 4 + 2], A0.w + sb[cg * 4 + 3]};
        float r1[4] = {A1.x + sb[cg * 4], A1.y + sb[cg * 4 + 1], A1.z + sb[cg * 4 + 2], A1.w + sb[cg * 4 + 3]};
        float* pred = out + (size_t)NN * 128;
#pragma unroll
        for (int i = 0; i < 4; i++) {
            int col = cg * 4 + i;
            if (col < 40) {
                if (gn0 < NN) pred[gn0 * 40 + col] = r0[i];
                if (gn1 < NN) pred[gn1 * 40 + col] = r1[i];
            }
        }
    }
}

// ---------------- launch ----------------
extern "C" void kernel_launch(void* const* d_in, const int* in_sizes, int n_in,
                              void* d_out, int out_size) {
    const float* feat0 = (const float*)d_in[0];
    const int*   src0  = (const int*)d_in[1];
    const int*   dst0  = (const int*)d_in[2];
    const float* feat1 = (const float*)d_in[3];
    const int*   src1  = (const int*)d_in[4];
    const int*   dst1  = (const int*)d_in[5];
    // Branch 1 (graph 0): W1a (layer1), W1b (layer2). Branch 2 (graph 1): W2a (layer1), W2b (layer2).
    const float* W1a = (const float*)d_in[6],  *B1a = (const float*)d_in[7];
    const float* W1b = (const float*)d_in[8],  *B1b = (const float*)d_in[9];
    const float* W2a = (const float*)d_in[10], *B2a = (const float*)d_in[11];
    const float* W2b = (const float*)d_in[12], *B2b = (const float*)d_in[13];
    const float* Wm1   = (const float*)d_in[14];
    const float* bm1   = (const float*)d_in[15];
    const float* gamma = (const float*)d_in[16];
    const float* beta  = (const float*)d_in[17];
    const float* Wm2   = (const float*)d_in[18];
    const float* bm2   = (const float*)d_in[19];
    float* out = (float*)d_out;

    const int EB = (EE + 255) / 256;        // 6250
    const int NB = (NN + 255) / 256;        // 391
    const int SB = (NN * 8) / 256;          // 3125 (exact)
    const int GB = (NN + 63) / 64;          // 1563

    k_hist     <<<dim3(EB, 2), 256>>>(src0, dst0, src1, dst1);
    k_scan1    <<<dim3(SCAN_NB, 2), 256>>>();
    k_scanB    <<<dim3(NB, 2), 256>>>();
    k_scatter  <<<dim3(EB, 2), 256>>>(src0, dst0, src1, dst1);
    k_scalefeat<<<dim3(SB, 2), 256>>>(feat0, feat1);
    k_spmm     <<<dim3(SB, 2), 256>>>(0);
    k_gemm     <<<dim3(GB, 2), 128>>>(W1a, B1a, W2a, B2a, 1);   // layer 1: graph0->W1a, graph1->W2a
    k_spmm     <<<dim3(SB, 2), 256>>>(1);
    k_gemm     <<<dim3(GB, 2), 128>>>(W1b, B1b, W2b, B2b, 0);   // layer 2: graph0->W1b, graph1->W2b
    k_colreduce<<<dim3(256, 2), 256>>>(0, gamma, beta);
    k_zy       <<<GB, 128>>>(Wm1, bm1, out);
    k_colreduce<<<dim3(512, 1), 256>>>(1, gamma, beta);
    k_head     <<<GB, 192>>>(Wm2, bm2, out);
}

// round 7
// speedup vs baseline: 1.1938x; 1.0232x over previous
#include <cuda_runtime.h>
#include <cuda_fp16.h>

#define NN 100000
#define EE 1600000
#define SCAN_NB 98   /* ceil(NN/1024) */

// ---------------- scratch (device globals; allocation-free) ----------------
__device__ int   g_deg_out[2][NN];   // zero-init; re-zeroed by k_scanB each call
__device__ int   g_deg_in [2][NN];   // zero-init; re-zeroed by k_scanB each call
__device__ int   g_scanS[2][NN];
__device__ int   g_blocksums[2][SCAN_NB];
__device__ int   g_rowptr[2][NN + 1];
__device__ int   g_cursor[2][NN];
__device__ int   g_csr[2][EE];
__device__ float g_ns[2][NN];
__device__ float g_nd[2][NN];
__device__ uint4 g_xh [2][NN * 8];   // half feature table (64 halfs/row = 128B)
__device__ uint2 g_hsh[2][NN * 16];  // half hidden table
__device__ float g_agg[2][NN * 64];
__device__ float g_h2 [2][NN * 64];
__device__ float g_y  [NN * 64];
__device__ float g_red[2][128];      // zero-init; re-zeroed by colreduce finalize
__device__ int   g_ticket[2];        // zero-init; reset by colreduce finalize
__device__ float g_mu  [2][64];
__device__ float g_istd[2][64];
__device__ float g_bnA[64];
__device__ float g_bnB[64];

__device__ __forceinline__ unsigned packh2(float a, float b) {
    __half2 h = __floats2half2_rn(a, b);
    return *reinterpret_cast<unsigned*>(&h);
}
__device__ __forceinline__ float2 unpackh2(unsigned u) {
    __half2 h = *reinterpret_cast<__half2*>(&u);
    return __half22float2(h);
}

// ---------------- degree histogram (both graphs, 2 edges/thread) ----------------
__global__ void k_hist(const int* __restrict__ s0, const int* __restrict__ d0,
                       const int* __restrict__ s1, const int* __restrict__ d1) {
    int g = blockIdx.y;
    const int* __restrict__ src = g ? s1 : s0;
    const int* __restrict__ dst = g ? d1 : d0;
    int i = (blockIdx.x * blockDim.x + threadIdx.x) * 2;
    if (i + 1 < EE) {
        int sA = src[i], sB = src[i + 1];
        int dA = dst[i], dB = dst[i + 1];
        atomicAdd(&g_deg_out[g][sA], 1);
        atomicAdd(&g_deg_out[g][sB], 1);
        atomicAdd(&g_deg_in [g][dA], 1);
        atomicAdd(&g_deg_in [g][dB], 1);
    } else if (i < EE) {
        atomicAdd(&g_deg_out[g][src[i]], 1);
        atomicAdd(&g_deg_in [g][dst[i]], 1);
    }
}

// ---------------- per-chunk inclusive scan of deg_in ----------------
__global__ void k_scan1() {
    int g = blockIdx.y;
    __shared__ int sm[256];
    int base = blockIdx.x * 1024 + threadIdx.x * 4;
    int v[4]; int s = 0;
#pragma unroll
    for (int t = 0; t < 4; t++) {
        v[t] = (base + t < NN) ? g_deg_in[g][base + t] : 0;
        s += v[t];
    }
    sm[threadIdx.x] = s;
    __syncthreads();
    for (int off = 1; off < 256; off <<= 1) {
        int add = (threadIdx.x >= off) ? sm[threadIdx.x - off] : 0;
        __syncthreads();
        sm[threadIdx.x] += add;
        __syncthreads();
    }
    int run = sm[threadIdx.x] - s;
#pragma unroll
    for (int t = 0; t < 4; t++) {
        run += v[t];
        if (base + t < NN) g_scanS[g][base + t] = run;
    }
    if (threadIdx.x == 255) g_blocksums[g][blockIdx.x] = sm[255];
}

// ------- fused: chunk-offset + rowptr/cursor + norms + degree re-zero -------
__global__ void __launch_bounds__(256) k_scanB() {
    int g = blockIdx.y;
    __shared__ int sred[256];
    int t = threadIdx.x;
    int cb = (blockIdx.x * 256) >> 10;
    sred[t] = (t < cb) ? g_blocksums[g][t] : 0;
    __syncthreads();
#pragma unroll
    for (int off = 128; off > 0; off >>= 1) {
        if (t < off) sred[t] += sred[t + off];
        __syncthreads();
    }
    int offset = sred[0];
    int i = blockIdx.x * 256 + t;
    if (i < NN) {
        int din  = g_deg_in[g][i];
        int dout = g_deg_out[g][i];
        int incl = g_scanS[g][i] + offset;
        int excl = incl - din;
        g_rowptr[g][i] = excl;
        g_cursor[g][i] = excl;
        if (i == NN - 1) g_rowptr[g][NN] = incl;
        float fo = (dout < 1) ? 1.f : (float)dout;
        float fi = (din  < 1) ? 1.f : (float)din;
        g_ns[g][i] = rsqrtf(fo);
        g_nd[g][i] = rsqrtf(fi);
        g_deg_out[g][i] = 0;
        g_deg_in [g][i] = 0;
    }
}

// ---------------- CSR scatter (counting sort by dst, 2 edges/thread) ----------------
__global__ void k_scatter(const int* __restrict__ s0, const int* __restrict__ d0,
                          const int* __restrict__ s1, const int* __restrict__ d1) {
    int g = blockIdx.y;
    const int* __restrict__ src = g ? s1 : s0;
    const int* __restrict__ dst = g ? d1 : d0;
    int i = (blockIdx.x * blockDim.x + threadIdx.x) * 2;
    if (i + 1 < EE) {
        int dA = dst[i], dB = dst[i + 1];
        int sA = src[i], sB = src[i + 1];
        int pA = atomicAdd(&g_cursor[g][dA], 1);
        int pB = atomicAdd(&g_cursor[g][dB], 1);
        g_csr[g][pA] = sA;
        g_csr[g][pB] = sB;
    } else if (i < EE) {
        int p = atomicAdd(&g_cursor[g][dst[i]], 1);
        g_csr[g][p] = src[i];
    }
}

// ---------------- xh = half(feat * ns) ----------------
__global__ void __launch_bounds__(256) k_scalefeat(const float* __restrict__ f0,
                                                   const float* __restrict__ f1) {
    int g = blockIdx.y;
    const float* __restrict__ feat = g ? f1 : f0;
    int idx = blockIdx.x * 256 + threadIdx.x;   // [0, NN*8)
    int node = idx >> 3, c = idx & 7;
    float s = g_ns[g][node];
    float4 v0 = ((const float4*)feat)[node * 16 + c * 2];
    float4 v1 = ((const float4*)feat)[node * 16 + c * 2 + 1];
    uint4 o;
    o.x = packh2(v0.x * s, v0.y * s);
    o.y = packh2(v0.z * s, v0.w * s);
    o.z = packh2(v1.x * s, v1.y * s);
    o.w = packh2(v1.z * s, v1.w * s);
    g_xh[g][idx] = o;
}

__device__ __forceinline__ void acc8(float2& p0, float2& p1, float2& p2, float2& p3,
                                     uint4 v) {
    float2 f;
    f = unpackh2(v.x); p0.x += f.x; p0.y += f.y;
    f = unpackh2(v.y); p1.x += f.x; p1.y += f.y;
    f = unpackh2(v.z); p2.x += f.x; p2.y += f.y;
    f = unpackh2(v.w); p3.x += f.x; p3.y += f.y;
}

// ------- gather SpMM (half rows, fp32 accum, 4-deep MLP): agg[d] = nd * sum xsrc[s] -------
// 8 lanes per dst node; lane c holds cols 8c..8c+7 (one uint4 = 8 halfs).
__global__ void __launch_bounds__(256) k_spmm(int lay) {
    int g = blockIdx.y;
    const uint4* __restrict__ table = lay ? (const uint4*)g_hsh[g] : g_xh[g];
    int t = blockIdx.x * 256 + threadIdx.x;     // [0, NN*8)
    int node = t >> 3, c = t & 7;
    int s0 = g_rowptr[g][node], s1 = g_rowptr[g][node + 1];
    int deg = s1 - s0;
    const int* __restrict__ csr = g_csr[g];
    float2 a0 = {0.f,0.f}, a1 = {0.f,0.f}, a2 = {0.f,0.f}, a3 = {0.f,0.f};
    float2 b0 = {0.f,0.f}, b1 = {0.f,0.f}, b2 = {0.f,0.f}, b3 = {0.f,0.f};
    int j = s0;
    for (int it = deg >> 2; it > 0; it--, j += 4) {
        int sA = __ldg(&csr[j]);
        int sB = __ldg(&csr[j + 1]);
        int sC = __ldg(&csr[j + 2]);
        int sD = __ldg(&csr[j + 3]);
        uint4 vA = __ldg(&table[sA * 8 + c]);
        uint4 vB = __ldg(&table[sB * 8 + c]);
        uint4 vC = __ldg(&table[sC * 8 + c]);
        uint4 vD = __ldg(&table[sD * 8 + c]);
        acc8(a0, a1, a2, a3, vA);
        acc8(b0, b1, b2, b3, vB);
        acc8(a0, a1, a2, a3, vC);
        acc8(b0, b1, b2, b3, vD);
    }
    for (int r = deg & 3; r > 0; r--, j++) {
        int sA = __ldg(&csr[j]);
        uint4 vA = __ldg(&table[sA * 8 + c]);
        acc8(a0, a1, a2, a3, vA);
    }
    float nd = g_nd[g][node];
    float4 o0, o1;
    o0.x = (a0.x + b0.x) * nd; o0.y = (a0.y + b0.y) * nd;
    o0.z = (a1.x + b1.x) * nd; o0.w = (a1.y + b1.y) * nd;
    o1.x = (a2.x + b2.x) * nd; o1.y = (a2.y + b2.y) * nd;
    o1.z = (a3.x + b3.x) * nd; o1.w = (a3.y + b3.y) * nd;
    ((float4*)&g_agg[g][node * 64])[c * 2]     = o0;
    ((float4*)&g_agg[g][node * 64])[c * 2 + 1] = o1;
}

// ------- node GEMM: out = act(agg @ W + b); layer1 -> half table, layer2 -> fp32 -------
__global__ void __launch_bounds__(128) k_gemm(const float* __restrict__ Wa,
                                              const float* __restrict__ ba,
                                              const float* __restrict__ Wb,
                                              const float* __restrict__ bb,
                                              int layer1) {
    int g = blockIdx.y;
    const float* __restrict__ W    = g ? Wb : Wa;
    const float* __restrict__ bias = g ? bb : ba;
    __shared__ float sW[64 * 64];
    __shared__ float sa[16][65];
    int tid = threadIdx.x;
    for (int idx = tid; idx < 1024; idx += 128)
        ((float4*)sW)[idx] = ((const float4*)W)[idx];
    int cg = tid & 15, ng = tid >> 4;
    float4 b4 = ((const float4*)bias)[cg];
    int blockbase = blockIdx.x * 64;
    for (int ch = 0; ch < 4; ch++) {
        int cb = blockbase + ch * 16;
        __syncthreads();
        for (int idx = tid; idx < 1024; idx += 128) {
            int n = idx >> 6, k = idx & 63;
            int gn = cb + n;
            sa[n][k] = (gn < NN) ? g_agg[g][gn * 64 + k] : 0.f;
        }
        __syncthreads();
        float4 A0 = make_float4(0.f, 0.f, 0.f, 0.f);
        float4 A1 = make_float4(0.f, 0.f, 0.f, 0.f);
#pragma unroll
        for (int k = 0; k < 64; k++) {
            float4 w = *(const float4*)&sW[k * 64 + cg * 4];
            float a0 = sa[ng * 2][k];
            float a1 = sa[ng * 2 + 1][k];
            A0.x = fmaf(a0, w.x, A0.x); A0.y = fmaf(a0, w.y, A0.y);
            A0.z = fmaf(a0, w.z, A0.z); A0.w = fmaf(a0, w.w, A0.w);
            A1.x = fmaf(a1, w.x, A1.x); A1.y = fmaf(a1, w.y, A1.y);
            A1.z = fmaf(a1, w.z, A1.z); A1.w = fmaf(a1, w.w, A1.w);
        }
        int gn0 = cb + ng * 2, gn1 = gn0 + 1;
        A0.x += b4.x; A0.y += b4.y; A0.z += b4.z; A0.w += b4.w;
        A1.x += b4.x; A1.y += b4.y; A1.z += b4.z; A1.w += b4.w;
        if (layer1) {
            if (gn0 < NN) {
                float s = g_ns[g][gn0];
                float x0 = fmaxf(A0.x, 0.f) * s, x1 = fmaxf(A0.y, 0.f) * s;
                float x2 = fmaxf(A0.z, 0.f) * s, x3 = fmaxf(A0.w, 0.f) * s;
                uint2 u; u.x = packh2(x0, x1); u.y = packh2(x2, x3);
                g_hsh[g][gn0 * 16 + cg] = u;
            }
            if (gn1 < NN) {
                float s = g_ns[g][gn1];
                float x0 = fmaxf(A1.x, 0.f) * s, x1 = fmaxf(A1.y, 0.f) * s;
                float x2 = fmaxf(A1.z, 0.f) * s, x3 = fmaxf(A1.w, 0.f) * s;
                uint2 u; u.x = packh2(x0, x1); u.y = packh2(x2, x3);
                g_hsh[g][gn1 * 16 + cg] = u;
            }
        } else {
            if (gn0 < NN) ((float4*)&g_h2[g][0])[gn0 * 16 + cg] = A0;
            if (gn1 < NN) ((float4*)&g_h2[g][0])[gn1 * 16 + cg] = A1;
        }
    }
}

// ------- column sum/sumsq reduce + fused finalize (last-block ticket) -------
// mode 0: z-stats (ddof=1) for g_h2[blockIdx.y]; mode 1: BN coeffs for g_y.
__global__ void __launch_bounds__(256) k_colreduce(int mode,
                                                   const float* __restrict__ gamma,
                                                   const float* __restrict__ beta) {
    int g = blockIdx.y;
    const float* __restrict__ buf = (mode == 0) ? g_h2[g] : g_y;
    __shared__ float ss[256], sq[256];
    __shared__ bool is_last;
    int col = threadIdx.x & 63;
    int rg = threadIdx.x >> 6;
    float s = 0.f, q = 0.f;
    for (int r = blockIdx.x * 4 + rg; r < NN; r += gridDim.x * 4) {
        float v = buf[r * 64 + col];
        s += v; q = fmaf(v, v, q);
    }
    ss[threadIdx.x] = s; sq[threadIdx.x] = q;
    __syncthreads();
    if (threadIdx.x < 128) {
        ss[threadIdx.x] += ss[threadIdx.x + 128];
        sq[threadIdx.x] += sq[threadIdx.x + 128];
    }
    __syncthreads();
    if (threadIdx.x < 64) {
        atomicAdd(&g_red[g][col],      ss[threadIdx.x] + ss[threadIdx.x + 64]);
        atomicAdd(&g_red[g][64 + col], sq[threadIdx.x] + sq[threadIdx.x + 64]);
    }
    __threadfence();
    if (threadIdx.x == 0) {
        int tk = atomicAdd(&g_ticket[g], 1);
        is_last = (tk == (int)gridDim.x - 1);
    }
    __syncthreads();
    if (is_last) {
        if (threadIdx.x < 64) {
            int c = threadIdx.x;
            float S = g_red[g][c], Q = g_red[g][64 + c];
            g_red[g][c] = 0.f; g_red[g][64 + c] = 0.f;
            float mu = S / (float)NN;
            if (mode == 0) {
                float var = (Q - (float)NN * mu * mu) / (float)(NN - 1);
                g_mu[g][c] = mu;
                g_istd[g][c] = rsqrtf(var);
            } else {
                float var = Q / (float)NN - mu * mu;
                float sc = gamma[c] * rsqrtf(var + 1e-5f);
                g_bnA[c] = sc;
                g_bnB[c] = beta[c] - mu * sc;
            }
        }
        if (threadIdx.x == 0) g_ticket[g] = 0;
    }
}

// ---------------- z1/z2 write + z = avg + y = z @ Wm1 + bm1 ----------------
__global__ void __launch_bounds__(128) k_zy(const float* __restrict__ Wm1,
                                            const float* __restrict__ bm1,
                                            float* __restrict__ out) {
    __shared__ float sW[64 * 64];
    __shared__ float sa[16][65];
    int tid = threadIdx.x;
    for (int idx = tid; idx < 1024; idx += 128)
        ((float4*)sW)[idx] = ((const float4*)Wm1)[idx];
    int cg = tid & 15, ng = tid >> 4;
    float4 b4 = ((const float4*)bm1)[cg];
    int blockbase = blockIdx.x * 64;
    for (int ch = 0; ch < 4; ch++) {
        int cb = blockbase + ch * 16;
        __syncthreads();
        for (int idx = tid; idx < 1024; idx += 128) {
            int n = idx >> 6, k = idx & 63;
            int gn = cb + n;
            float v = 0.f;
            if (gn < NN) {
                float z1 = (g_h2[0][gn * 64 + k] - g_mu[0][k]) * g_istd[0][k];
                float z2 = (g_h2[1][gn * 64 + k] - g_mu[1][k]) * g_istd[1][k];
                out[gn * 64 + k] = z1;
                out[NN * 64 + gn * 64 + k] = z2;
                v = 0.5f * (z1 + z2);
            }
            sa[n][k] = v;
        }
        __syncthreads();
        float4 A0 = make_float4(0.f, 0.f, 0.f, 0.f);
        float4 A1 = make_float4(0.f, 0.f, 0.f, 0.f);
#pragma unroll
        for (int k = 0; k < 64; k++) {
            float4 w = *(const float4*)&sW[k * 64 + cg * 4];
            float a0 = sa[ng * 2][k];
            float a1 = sa[ng * 2 + 1][k];
            A0.x = fmaf(a0, w.x, A0.x); A0.y = fmaf(a0, w.y, A0.y);
            A0.z = fmaf(a0, w.z, A0.z); A0.w = fmaf(a0, w.w, A0.w);
            A1.x = fmaf(a1, w.x, A1.x); A1.y = fmaf(a1, w.y, A1.y);
            A1.z = fmaf(a1, w.z, A1.z); A1.w = fmaf(a1, w.w, A1.w);
        }
        int gn0 = cb + ng * 2, gn1 = gn0 + 1;
        A0.x += b4.x; A0.y += b4.y; A0.z += b4.z; A0.w += b4.w;
        A1.x += b4.x; A1.y += b4.y; A1.z += b4.z; A1.w += b4.w;
        if (gn0 < NN) ((float4*)g_y)[gn0 * 16 + cg] = A0;
        if (gn1 < NN) ((float4*)g_y)[gn1 * 16 + cg] = A1;
    }
}

// ---------------- head: relu(BN(y)) @ Wm2 + bm2 ----------------
__global__ void __launch_bounds__(192) k_head(const float* __restrict__ W2,
                                              const float* __restrict__ b2,
                                              float* __restrict__ out) {
    __shared__ float sW2[64 * 48];
    __shared__ float st[32][65];
    __shared__ float sb[48];
    int tid = threadIdx.x;
    for (int idx = tid; idx < 64 * 12; idx += 192) {
        int k = idx / 12, c = idx % 12;
        float4 v = make_float4(0.f, 0.f, 0.f, 0.f);
        if (c < 10) v = *(const float4*)&W2[k * 40 + c * 4];
        ((float4*)sW2)[k * 12 + c] = v;
    }
    if (tid < 48) sb[tid] = (tid < 40) ? b2[tid] : 0.f;
    int cg = tid % 12, ng = tid / 12;
    int blockbase = blockIdx.x * 64;
    for (int ch = 0; ch < 2; ch++) {
        int cb = blockbase + ch * 32;
        __syncthreads();
        for (int idx = tid; idx < 2048; idx += 192) {
            int n = idx >> 6, k = idx & 63;
            int gn = cb + n;
            float v = 0.f;
            if (gn < NN) {
                v = g_y[gn * 64 + k] * g_bnA[k] + g_bnB[k];
                v = fmaxf(v, 0.f);
            }
            st[n][k] = v;
        }
        __syncthreads();
        float4 A0 = make_float4(0.f, 0.f, 0.f, 0.f);
        float4 A1 = make_float4(0.f, 0.f, 0.f, 0.f);
#pragma unroll
        for (int k = 0; k < 64; k++) {
            float4 w = ((float4*)sW2)[k * 12 + cg];
            float a0 = st[ng * 2][k];
            float a1 = st[ng * 2 + 1][k];
            A0.x = fmaf(a0, w.x, A0.x); A0.y = fmaf(a0, w.y, A0.y);
            A0.z = fmaf(a0, w.z, A0.z); A0.w = fmaf(a0, w.w, A0.w);
            A1.x = fmaf(a1, w.x, A1.x); A1.y = fmaf(a1, w.y, A1.y);
            A1.z = fmaf(a1, w.z, A1.z); A1.w = fmaf(a1, w.w, A1.w);
        }
        int gn0 = cb + ng * 2, gn1 = gn0 + 1;
        float r0[4] = {A0.x + sb[cg * 4], A0.y + sb[cg * 4 + 1], A0.z + sb[cg * 4 + 2], A0.w + sb[cg * 4 + 3]};
        float r1[4] = {A1.x + sb[cg * 4], A1.y + sb[cg * 4 + 1], A1.z + sb[cg * 4 + 2], A1.w + sb[cg * 4 + 3]};
        float* pred = out + (size_t)NN * 128;
#pragma unroll
        for (int i = 0; i < 4; i++) {
            int col = cg * 4 + i;
            if (col < 40) {
                if (gn0 < NN) pred[gn0 * 40 + col] = r0[i];
                if (gn1 < NN) pred[gn1 * 40 + col] = r1[i];
            }
        }
    }
}

// ---------------- launch ----------------
extern "C" void kernel_launch(void* const* d_in, const int* in_sizes, int n_in,
                              void* d_out, int out_size) {
    const float* feat0 = (const float*)d_in[0];
    const int*   src0  = (const int*)d_in[1];
    const int*   dst0  = (const int*)d_in[2];
    const float* feat1 = (const float*)d_in[3];
    const int*   src1  = (const int*)d_in[4];
    const int*   dst1  = (const int*)d_in[5];
    // Branch 1 (graph 0): W1a (layer1), W1b (layer2). Branch 2 (graph 1): W2a (layer1), W2b (layer2).
    const float* W1a = (const float*)d_in[6],  *B1a = (const float*)d_in[7];
    const float* W1b = (const float*)d_in[8],  *B1b = (const float*)d_in[9];
    const float* W2a = (const float*)d_in[10], *B2a = (const float*)d_in[11];
    const float* W2b = (const float*)d_in[12], *B2b = (const float*)d_in[13];
    const float* Wm1   = (const float*)d_in[14];
    const float* bm1   = (const float*)d_in[15];
    const float* gamma = (const float*)d_in[16];
    const float* beta  = (const float*)d_in[17];
    const float* Wm2   = (const float*)d_in[18];
    const float* bm2   = (const float*)d_in[19];
    float* out = (float*)d_out;

    const int E2 = (EE / 2 + 255) / 256;    // 3125 (2 edges/thread)
    const int NB = (NN + 255) / 256;        // 391
    const int SB = (NN * 8) / 256;          // 3125 (exact)
    const int GB = (NN + 63) / 64;          // 1563

    k_hist     <<<dim3(E2, 2), 256>>>(src0, dst0, src1, dst1);
    k_scan1    <<<dim3(SCAN_NB, 2), 256>>>();
    k_scanB    <<<dim3(NB, 2), 256>>>();
    k_scatter  <<<dim3(E2, 2), 256>>>(src0, dst0, src1, dst1);
    k_scalefeat<<<dim3(SB, 2), 256>>>(feat0, feat1);
    k_spmm     <<<dim3(SB, 2), 256>>>(0);
    k_gemm     <<<dim3(GB, 2), 128>>>(W1a, B1a, W2a, B2a, 1);   // layer 1: graph0->W1a, graph1->W2a
    k_spmm     <<<dim3(SB, 2), 256>>>(1);
    k_gemm     <<<dim3(GB, 2), 128>>>(W1b, B1b, W2b, B2b, 0);   // layer 2: graph0->W1b, graph1->W2b
    k_colreduce<<<dim3(256, 2), 256>>>(0, gamma, beta);
    k_zy       <<<GB, 128>>>(Wm1, bm1, out);
    k_colreduce<<<dim3(512, 1), 256>>>(1, gamma, beta);
    k_head     <<<GB, 192>>>(Wm2, bm2, out);
}

// round 9
// speedup vs baseline: 1.3488x; 1.1298x over previous
#include <cuda_runtime.h>
#include <cuda_fp16.h>

#define NN 100000
#define EE 1600000
#define SCAN_NB 98   /* ceil(NN/1024) */

// ---------------- scratch (device globals; allocation-free) ----------------
__device__ int   g_deg_out[2][NN];   // zero-init; re-zeroed by k_scanB each call
__device__ int   g_deg_in [2][NN];   // zero-init; re-zeroed by k_scanB each call
__device__ int   g_scanS[2][NN];
__device__ int   g_blocksums[2][SCAN_NB];
__device__ int   g_rowptr[2][NN + 1];
__device__ int   g_cursor[2][NN];
__device__ int   g_csr[2][EE];
__device__ float g_ns[2][NN];
__device__ float g_nd[2][NN];
__device__ uint4 g_xh [2][NN * 8];   // half feature table (64 halfs/row = 128B)
__device__ uint2 g_hsh[2][NN * 16];  // half hidden table
__device__ uint4 g_aggh[2][NN * 8];  // half aggregated rows (spmm -> gemm)
__device__ float g_h2 [2][NN * 64];
__device__ float g_y  [NN * 64];
__device__ float g_red[2][128];      // zero-init; re-zeroed by finalize
__device__ int   g_ticket[2];        // zero-init; reset by finalize
__device__ float g_mu  [2][64];
__device__ float g_istd[2][64];
__device__ float g_bnA[64];
__device__ float g_bnB[64];

__device__ __forceinline__ unsigned packh2(float a, float b) {
    __half2 h = __floats2half2_rn(a, b);
    return *reinterpret_cast<unsigned*>(&h);
}
__device__ __forceinline__ float2 unpackh2(unsigned u) {
    __half2 h = *reinterpret_cast<__half2*>(&u);
    return __half22float2(h);
}

// ---------------- degree histogram (both graphs, 2 edges/thread) ----------------
__global__ void k_hist(const int* __restrict__ s0, const int* __restrict__ d0,
                       const int* __restrict__ s1, const int* __restrict__ d1) {
    int g = blockIdx.y;
    const int* __restrict__ src = g ? s1 : s0;
    const int* __restrict__ dst = g ? d1 : d0;
    int i = (blockIdx.x * blockDim.x + threadIdx.x) * 2;
    if (i + 1 < EE) {
        int sA = src[i], sB = src[i + 1];
        int dA = dst[i], dB = dst[i + 1];
        atomicAdd(&g_deg_out[g][sA], 1);
        atomicAdd(&g_deg_out[g][sB], 1);
        atomicAdd(&g_deg_in [g][dA], 1);
        atomicAdd(&g_deg_in [g][dB], 1);
    } else if (i < EE) {
        atomicAdd(&g_deg_out[g][src[i]], 1);
        atomicAdd(&g_deg_in [g][dst[i]], 1);
    }
}

// ---------------- per-chunk inclusive scan of deg_in ----------------
__global__ void k_scan1() {
    int g = blockIdx.y;
    __shared__ int sm[256];
    int base = blockIdx.x * 1024 + threadIdx.x * 4;
    int v[4]; int s = 0;
#pragma unroll
    for (int t = 0; t < 4; t++) {
        v[t] = (base + t < NN) ? g_deg_in[g][base + t] : 0;
        s += v[t];
    }
    sm[threadIdx.x] = s;
    __syncthreads();
    for (int off = 1; off < 256; off <<= 1) {
        int add = (threadIdx.x >= off) ? sm[threadIdx.x - off] : 0;
        __syncthreads();
        sm[threadIdx.x] += add;
        __syncthreads();
    }
    int run = sm[threadIdx.x] - s;
#pragma unroll
    for (int t = 0; t < 4; t++) {
        run += v[t];
        if (base + t < NN) g_scanS[g][base + t] = run;
    }
    if (threadIdx.x == 255) g_blocksums[g][blockIdx.x] = sm[255];
}

// ------- fused: chunk-offset + rowptr/cursor + norms + degree re-zero -------
__global__ void __launch_bounds__(256) k_scanB() {
    int g = blockIdx.y;
    __shared__ int sred[256];
    int t = threadIdx.x;
    int cb = (blockIdx.x * 256) >> 10;
    sred[t] = (t < cb) ? g_blocksums[g][t] : 0;
    __syncthreads();
#pragma unroll
    for (int off = 128; off > 0; off >>= 1) {
        if (t < off) sred[t] += sred[t + off];
        __syncthreads();
    }
    int offset = sred[0];
    int i = blockIdx.x * 256 + t;
    if (i < NN) {
        int din  = g_deg_in[g][i];
        int dout = g_deg_out[g][i];
        int incl = g_scanS[g][i] + offset;
        int excl = incl - din;
        g_rowptr[g][i] = excl;
        g_cursor[g][i] = excl;
        if (i == NN - 1) g_rowptr[g][NN] = incl;
        float fo = (dout < 1) ? 1.f : (float)dout;
        float fi = (din  < 1) ? 1.f : (float)din;
        g_ns[g][i] = rsqrtf(fo);
        g_nd[g][i] = rsqrtf(fi);
        g_deg_out[g][i] = 0;
        g_deg_in [g][i] = 0;
    }
}

// ---------------- CSR scatter (counting sort by dst, 2 edges/thread) ----------------
__global__ void k_scatter(const int* __restrict__ s0, const int* __restrict__ d0,
                          const int* __restrict__ s1, const int* __restrict__ d1) {
    int g = blockIdx.y;
    const int* __restrict__ src = g ? s1 : s0;
    const int* __restrict__ dst = g ? d1 : d0;
    int i = (blockIdx.x * blockDim.x + threadIdx.x) * 2;
    if (i + 1 < EE) {
        int dA = dst[i], dB = dst[i + 1];
        int sA = src[i], sB = src[i + 1];
        int pA = atomicAdd(&g_cursor[g][dA], 1);
        int pB = atomicAdd(&g_cursor[g][dB], 1);
        g_csr[g][pA] = sA;
        g_csr[g][pB] = sB;
    } else if (i < EE) {
        int p = atomicAdd(&g_cursor[g][dst[i]], 1);
        g_csr[g][p] = src[i];
    }
}

// ---------------- xh = half(feat * ns) ----------------
__global__ void __launch_bounds__(256) k_scalefeat(const float* __restrict__ f0,
                                                   const float* __restrict__ f1) {
    int g = blockIdx.y;
    const float* __restrict__ feat = g ? f1 : f0;
    int idx = blockIdx.x * 256 + threadIdx.x;   // [0, NN*8)
    int node = idx >> 3, c = idx & 7;
    float s = g_ns[g][node];
    float4 v0 = ((const float4*)feat)[node * 16 + c * 2];
    float4 v1 = ((const float4*)feat)[node * 16 + c * 2 + 1];
    uint4 o;
    o.x = packh2(v0.x * s, v0.y * s);
    o.y = packh2(v0.z * s, v0.w * s);
    o.z = packh2(v1.x * s, v1.y * s);
    o.w = packh2(v1.z * s, v1.w * s);
    g_xh[g][idx] = o;
}

__device__ __forceinline__ void acc8(float2& p0, float2& p1, float2& p2, float2& p3,
                                     uint4 v) {
    float2 f;
    f = unpackh2(v.x); p0.x += f.x; p0.y += f.y;
    f = unpackh2(v.y); p1.x += f.x; p1.y += f.y;
    f = unpackh2(v.z); p2.x += f.x; p2.y += f.y;
    f = unpackh2(v.w); p3.x += f.x; p3.y += f.y;
}

// ------- gather SpMM (half in, half out, fp32 accum): aggh[d] = nd * sum xsrc[s] -------
__global__ void __launch_bounds__(256) k_spmm(int lay) {
    int g = blockIdx.y;
    const uint4* __restrict__ table = lay ? (const uint4*)g_hsh[g] : g_xh[g];
    int t = blockIdx.x * 256 + threadIdx.x;     // [0, NN*8)
    int node = t >> 3, c = t & 7;
    int s0 = g_rowptr[g][node], s1 = g_rowptr[g][node + 1];
    int deg = s1 - s0;
    const int* __restrict__ csr = g_csr[g];
    float2 a0 = {0.f,0.f}, a1 = {0.f,0.f}, a2 = {0.f,0.f}, a3 = {0.f,0.f};
    float2 b0 = {0.f,0.f}, b1 = {0.f,0.f}, b2 = {0.f,0.f}, b3 = {0.f,0.f};
    int j = s0;
    for (int it = deg >> 2; it > 0; it--, j += 4) {
        int sA = __ldg(&csr[j]);
        int sB = __ldg(&csr[j + 1]);
        int sC = __ldg(&csr[j + 2]);
        int sD = __ldg(&csr[j + 3]);
        uint4 vA = __ldg(&table[sA * 8 + c]);
        uint4 vB = __ldg(&table[sB * 8 + c]);
        uint4 vC = __ldg(&table[sC * 8 + c]);
        uint4 vD = __ldg(&table[sD * 8 + c]);
        acc8(a0, a1, a2, a3, vA);
        acc8(b0, b1, b2, b3, vB);
        acc8(a0, a1, a2, a3, vC);
        acc8(b0, b1, b2, b3, vD);
    }
    for (int r = deg & 3; r > 0; r--, j++) {
        int sA = __ldg(&csr[j]);
        uint4 vA = __ldg(&table[sA * 8 + c]);
        acc8(a0, a1, a2, a3, vA);
    }
    float nd = g_nd[g][node];
    uint4 o;
    o.x = packh2((a0.x + b0.x) * nd, (a0.y + b0.y) * nd);
    o.y = packh2((a1.x + b1.x) * nd, (a1.y + b1.y) * nd);
    o.z = packh2((a2.x + b2.x) * nd, (a2.y + b2.y) * nd);
    o.w = packh2((a3.x + b3.x) * nd, (a3.y + b3.y) * nd);
    g_aggh[g][t] = o;
}

// ------- node GEMM: out = act(aggh @ W + b); layer1 -> half table; layer2 -> fp32 + fused z-stats -------
__global__ void __launch_bounds__(128) k_gemm(const float* __restrict__ Wa,
                                              const float* __restrict__ ba,
                                              const float* __restrict__ Wb,
                                              const float* __restrict__ bb,
                                              int layer1) {
    int g = blockIdx.y;
    const float* __restrict__ W    = g ? Wb : Wa;
    const float* __restrict__ bias = g ? bb : ba;
    __shared__ float sW[64 * 64];
    __shared__ float sa[16][65];
    __shared__ float sS[4][64], sQ[4][64];
    int tid = threadIdx.x;
    for (int idx = tid; idx < 1024; idx += 128)
        ((float4*)sW)[idx] = ((const float4*)W)[idx];
    int cg = tid & 15, ng = tid >> 4;
    float4 b4 = ((const float4*)bias)[cg];
    int blockbase = blockIdx.x * 64;
    float4 stS = make_float4(0.f, 0.f, 0.f, 0.f);
    float4 stQ = make_float4(0.f, 0.f, 0.f, 0.f);
    for (int ch = 0; ch < 4; ch++) {
        int cb = blockbase + ch * 16;
        __syncthreads();
        // stage half agg rows -> fp32 smem (16 nodes x 64)
        for (int idx = tid; idx < 256; idx += 128) {
            int n = idx >> 4, k4 = idx & 15;
            int gn = cb + n;
            float2 f0 = {0.f,0.f}, f1 = {0.f,0.f};
            if (gn < NN) {
                uint2 u = ((const uint2*)g_aggh[g])[gn * 16 + k4];
                f0 = unpackh2(u.x);
                f1 = unpackh2(u.y);
            }
            sa[n][k4 * 4]     = f0.x;
            sa[n][k4 * 4 + 1] = f0.y;
            sa[n][k4 * 4 + 2] = f1.x;
            sa[n][k4 * 4 + 3] = f1.y;
        }
        __syncthreads();
        float4 A0 = make_float4(0.f, 0.f, 0.f, 0.f);
        float4 A1 = make_float4(0.f, 0.f, 0.f, 0.f);
#pragma unroll
        for (int k = 0; k < 64; k++) {
            float4 w = *(const float4*)&sW[k * 64 + cg * 4];
            float a0 = sa[ng * 2][k];
            float a1 = sa[ng * 2 + 1][k];
            A0.x = fmaf(a0, w.x, A0.x); A0.y = fmaf(a0, w.y, A0.y);
            A0.z = fmaf(a0, w.z, A0.z); A0.w = fmaf(a0, w.w, A0.w);
            A1.x = fmaf(a1, w.x, A1.x); A1.y = fmaf(a1, w.y, A1.y);
            A1.z = fmaf(a1, w.z, A1.z); A1.w = fmaf(a1, w.w, A1.w);
        }
        int gn0 = cb + ng * 2, gn1 = gn0 + 1;
        A0.x += b4.x; A0.y += b4.y; A0.z += b4.z; A0.w += b4.w;
        A1.x += b4.x; A1.y += b4.y; A1.z += b4.z; A1.w += b4.w;
        if (layer1) {
            if (gn0 < NN) {
                float s = g_ns[g][gn0];
                uint2 u;
                u.x = packh2(fmaxf(A0.x, 0.f) * s, fmaxf(A0.y, 0.f) * s);
                u.y = packh2(fmaxf(A0.z, 0.f) * s, fmaxf(A0.w, 0.f) * s);
                g_hsh[g][gn0 * 16 + cg] = u;
            }
            if (gn1 < NN) {
                float s = g_ns[g][gn1];
                uint2 u;
                u.x = packh2(fmaxf(A1.x, 0.f) * s, fmaxf(A1.y, 0.f) * s);
                u.y = packh2(fmaxf(A1.z, 0.f) * s, fmaxf(A1.w, 0.f) * s);
                g_hsh[g][gn1 * 16 + cg] = u;
            }
        } else {
            if (gn0 < NN) {
                ((float4*)&g_h2[g][0])[gn0 * 16 + cg] = A0;
                stS.x += A0.x; stS.y += A0.y; stS.z += A0.z; stS.w += A0.w;
                stQ.x = fmaf(A0.x, A0.x, stQ.x); stQ.y = fmaf(A0.y, A0.y, stQ.y);
                stQ.z = fmaf(A0.z, A0.z, stQ.z); stQ.w = fmaf(A0.w, A0.w, stQ.w);
            }
            if (gn1 < NN) {
                ((float4*)&g_h2[g][0])[gn1 * 16 + cg] = A1;
                stS.x += A1.x; stS.y += A1.y; stS.z += A1.z; stS.w += A1.w;
                stQ.x = fmaf(A1.x, A1.x, stQ.x); stQ.y = fmaf(A1.y, A1.y, stQ.y);
                stQ.z = fmaf(A1.z, A1.z, stQ.z); stQ.w = fmaf(A1.w, A1.w, stQ.w);
            }
        }
    }
    if (!layer1) {
        // pair-reduce lanes (tid, tid^16) share cg
        stS.x += __shfl_xor_sync(0xffffffffu, stS.x, 16);
        stS.y += __shfl_xor_sync(0xffffffffu, stS.y, 16);
        stS.z += __shfl_xor_sync(0xffffffffu, stS.z, 16);
        stS.w += __shfl_xor_sync(0xffffffffu, stS.w, 16);
        stQ.x += __shfl_xor_sync(0xffffffffu, stQ.x, 16);
        stQ.y += __shfl_xor_sync(0xffffffffu, stQ.y, 16);
        stQ.z += __shfl_xor_sync(0xffffffffu, stQ.z, 16);
        stQ.w += __shfl_xor_sync(0xffffffffu, stQ.w, 16);
        int wid = tid >> 5, lane = tid & 31;
        __syncthreads();
        if (lane < 16) {
            sS[wid][lane * 4]     = stS.x; sS[wid][lane * 4 + 1] = stS.y;
            sS[wid][lane * 4 + 2] = stS.z; sS[wid][lane * 4 + 3] = stS.w;
            sQ[wid][lane * 4]     = stQ.x; sQ[wid][lane * 4 + 1] = stQ.y;
            sQ[wid][lane * 4 + 2] = stQ.z; sQ[wid][lane * 4 + 3] = stQ.w;
        }
        __syncthreads();
        __shared__ bool is_last;
        if (tid < 64) {
            float s = sS[0][tid] + sS[1][tid] + sS[2][tid] + sS[3][tid];
            float q = sQ[0][tid] + sQ[1][tid] + sQ[2][tid] + sQ[3][tid];
            atomicAdd(&g_red[g][tid], s);
            atomicAdd(&g_red[g][64 + tid], q);
        }
        __threadfence();
        if (tid == 0) {
            int tk = atomicAdd(&g_ticket[g], 1);
            is_last = (tk == (int)gridDim.x - 1);
        }
        __syncthreads();
        if (is_last) {
            if (tid < 64) {
                float S = g_red[g][tid], Q = g_red[g][64 + tid];
                g_red[g][tid] = 0.f; g_red[g][64 + tid] = 0.f;
                float mu = S / (float)NN;
                float var = (Q - (float)NN * mu * mu) / (float)(NN - 1);
                g_mu[g][tid] = mu;
                g_istd[g][tid] = rsqrtf(var);
            }
            if (tid == 0) g_ticket[g] = 0;
        }
    }
}

// ------- z1/z2 write + z = avg + y = z @ Wm1 + bm1 + fused BN stats -------
__global__ void __launch_bounds__(128) k_zy(const float* __restrict__ Wm1,
                                            const float* __restrict__ bm1,
                                            const float* __restrict__ gamma,
                                            const float* __restrict__ beta,
                                            float* __restrict__ out) {
    __shared__ float sW[64 * 64];
    __shared__ float sa[16][65];
    __shared__ float sS[4][64], sQ[4][64];
    int tid = threadIdx.x;
    for (int idx = tid; idx < 1024; idx += 128)
        ((float4*)sW)[idx] = ((const float4*)Wm1)[idx];
    int cg = tid & 15, ng = tid >> 4;
    float4 b4 = ((const float4*)bm1)[cg];
    int blockbase = blockIdx.x * 64;
    float4 stS = make_float4(0.f, 0.f, 0.f, 0.f);
    float4 stQ = make_float4(0.f, 0.f, 0.f, 0.f);
    for (int ch = 0; ch < 4; ch++) {
        int cb = blockbase + ch * 16;
        __syncthreads();
        for (int idx = tid; idx < 1024; idx += 128) {
            int n = idx >> 6, k = idx & 63;
            int gn = cb + n;
            float v = 0.f;
            if (gn < NN) {
                float z1 = (g_h2[0][gn * 64 + k] - g_mu[0][k]) * g_istd[0][k];
                float z2 = (g_h2[1][gn * 64 + k] - g_mu[1][k]) * g_istd[1][k];
                out[gn * 64 + k] = z1;
                out[NN * 64 + gn * 64 + k] = z2;
                v = 0.5f * (z1 + z2);
            }
            sa[n][k] = v;
        }
        __syncthreads();
        float4 A0 = make_float4(0.f, 0.f, 0.f, 0.f);
        float4 A1 = make_float4(0.f, 0.f, 0.f, 0.f);
#pragma unroll
        for (int k = 0; k < 64; k++) {
            float4 w = *(const float4*)&sW[k * 64 + cg * 4];
            float a0 = sa[ng * 2][k];
            float a1 = sa[ng * 2 + 1][k];
            A0.x = fmaf(a0, w.x, A0.x); A0.y = fmaf(a0, w.y, A0.y);
            A0.z = fmaf(a0, w.z, A0.z); A0.w = fmaf(a0, w.w, A0.w);
            A1.x = fmaf(a1, w.x, A1.x); A1.y = fmaf(a1, w.y, A1.y);
            A1.z = fmaf(a1, w.z, A1.z); A1.w = fmaf(a1, w.w, A1.w);
        }
        int gn0 = cb + ng * 2, gn1 = gn0 + 1;
        A0.x += b4.x; A0.y += b4.y; A0.z += b4.z; A0.w += b4.w;
        A1.x += b4.x; A1.y += b4.y; A1.z += b4.z; A1.w += b4.w;
        if (gn0 < NN) {
            ((float4*)g_y)[gn0 * 16 + cg] = A0;
            stS.x += A0.x; stS.y += A0.y; stS.z += A0.z; stS.w += A0.w;
            stQ.x = fmaf(A0.x, A0.x, stQ.x); stQ.y = fmaf(A0.y, A0.y, stQ.y);
            stQ.z = fmaf(A0.z, A0.z, stQ.z); stQ.w = fmaf(A0.w, A0.w, stQ.w);
        }
        if (gn1 < NN) {
            ((float4*)g_y)[gn1 * 16 + cg] = A1;
            stS.x += A1.x; stS.y += A1.y; stS.z += A1.z; stS.w += A1.w;
            stQ.x = fmaf(A1.x, A1.x, stQ.x); stQ.y = fmaf(A1.y, A1.y, stQ.y);
            stQ.z = fmaf(A1.z, A1.z, stQ.z); stQ.w = fmaf(A1.w, A1.w, stQ.w);
        }
    }
    stS.x += __shfl_xor_sync(0xffffffffu, stS.x, 16);
    stS.y += __shfl_xor_sync(0xffffffffu, stS.y, 16);
    stS.z += __shfl_xor_sync(0xffffffffu, stS.z, 16);
    stS.w += __shfl_xor_sync(0xffffffffu, stS.w, 16);
    stQ.x += __shfl_xor_sync(0xffffffffu, stQ.x, 16);
    stQ.y += __shfl_xor_sync(0xffffffffu, stQ.y, 16);
    stQ.z += __shfl_xor_sync(0xffffffffu, stQ.z, 16);
    stQ.w += __shfl_xor_sync(0xffffffffu, stQ.w, 16);
    int wid = tid >> 5, lane = tid & 31;
    __syncthreads();
    if (lane < 16) {
        sS[wid][lane * 4]     = stS.x; sS[wid][lane * 4 + 1] = stS.y;
        sS[wid][lane * 4 + 2] = stS.z; sS[wid][lane * 4 + 3] = stS.w;
        sQ[wid][lane * 4]     = stQ.x; sQ[wid][lane * 4 + 1] = stQ.y;
        sQ[wid][lane * 4 + 2] = stQ.z; sQ[wid][lane * 4 + 3] = stQ.w;
    }
    __syncthreads();
    __shared__ bool is_last;
    if (tid < 64) {
        float s = sS[0][tid] + sS[1][tid] + sS[2][tid] + sS[3][tid];
        float q = sQ[0][tid] + sQ[1][tid] + sQ[2][tid] + sQ[3][tid];
        atomicAdd(&g_red[0][tid], s);
        atomicAdd(&g_red[0][64 + tid], q);
    }
    __threadfence();
    if (tid == 0) {
        int tk = atomicAdd(&g_ticket[0], 1);
        is_last = (tk == (int)gridDim.x - 1);
    }
    __syncthreads();
    if (is_last) {
        if (tid < 64) {
            float S = g_red[0][tid], Q = g_red[0][64 + tid];
            g_red[0][tid] = 0.f; g_red[0][64 + tid] = 0.f;
            float mu = S / (float)NN;
            float var = Q / (float)NN - mu * mu;
            float sc = gamma[tid] * rsqrtf(var + 1e-5f);
            g_bnA[tid] = sc;
            g_bnB[tid] = beta[tid] - mu * sc;
        }
        if (tid == 0) g_ticket[0] = 0;
    }
}

// ---------------- head: relu(BN(y)) @ Wm2 + bm2 ----------------
__global__ void __launch_bounds__(192) k_head(const float* __restrict__ W2,
                                              const float* __restrict__ b2,
                                              float* __restrict__ out) {
    __shared__ float sW2[64 * 48];
    __shared__ float st[32][65];
    __shared__ float sb[48];
    int tid = threadIdx.x;
    for (int idx = tid; idx < 64 * 12; idx += 192) {
        int k = idx / 12, c = idx % 12;
        float4 v = make_float4(0.f, 0.f, 0.f, 0.f);
        if (c < 10) v = *(const float4*)&W2[k * 40 + c * 4];
        ((float4*)sW2)[k * 12 + c] = v;
    }
    if (tid < 48) sb[tid] = (tid < 40) ? b2[tid] : 0.f;
    int cg = tid % 12, ng = tid / 12;
    int blockbase = blockIdx.x * 64;
    for (int ch = 0; ch < 2; ch++) {
        int cb = blockbase + ch * 32;
        __syncthreads();
        for (int idx = tid; idx < 2048; idx += 192) {
            int n = idx >> 6, k = idx & 63;
            int gn = cb + n;
            float v = 0.f;
            if (gn < NN) {
                v = g_y[gn * 64 + k] * g_bnA[k] + g_bnB[k];
                v = fmaxf(v, 0.f);
            }
            st[n][k] = v;
        }
        __syncthreads();
        float4 A0 = make_float4(0.f, 0.f, 0.f, 0.f);
        float4 A1 = make_float4(0.f, 0.f, 0.f, 0.f);
#pragma unroll
        for (int k = 0; k < 64; k++) {
            float4 w = ((float4*)sW2)[k * 12 + cg];
            float a0 = st[ng * 2][k];
            float a1 = st[ng * 2 + 1][k];
            A0.x = fmaf(a0, w.x, A0.x); A0.y = fmaf(a0, w.y, A0.y);
            A0.z = fmaf(a0, w.z, A0.z); A0.w = fmaf(a0, w.w, A0.w);
            A1.x = fmaf(a1, w.x, A1.x); A1.y = fmaf(a1, w.y, A1.y);
            A1.z = fmaf(a1, w.z, A1.z); A1.w = fmaf(a1, w.w, A1.w);
        }
        int gn0 = cb + ng * 2, gn1 = gn0 + 1;
        float r0[4] = {A0.x + sb[cg * 4], A0.y + sb[cg * 4 + 1], A0.z + sb[cg * 4 + 2], A0.w + sb[cg * 4 + 3]};
        float r1[4] = {A1.x + sb[cg * 4], A1.y + sb[cg * 4 + 1], A1.z + sb[cg * 4 + 2], A1.w + sb[cg * 4 + 3]};
        float* pred = out + (size_t)NN * 128;
#pragma unroll
        for (int i = 0; i < 4; i++) {
            int col = cg * 4 + i;
            if (col < 40) {
                if (gn0 < NN) pred[gn0 * 40 + col] = r0[i];
                if (gn1 < NN) pred[gn1 * 40 + col] = r1[i];
            }
        }
    }
}

// ---------------- launch ----------------
extern "C" void kernel_launch(void* const* d_in, const int* in_sizes, int n_in,
                              void* d_out, int out_size) {
    const float* feat0 = (const float*)d_in[0];
    const int*   src0  = (const int*)d_in[1];
    const int*   dst0  = (const int*)d_in[2];
    const float* feat1 = (const float*)d_in[3];
    const int*   src1  = (const int*)d_in[4];
    const int*   dst1  = (const int*)d_in[5];
    // Branch 1 (graph 0): W1a (layer1), W1b (layer2). Branch 2 (graph 1): W2a (layer1), W2b (layer2).
    const float* W1a = (const float*)d_in[6],  *B1a = (const float*)d_in[7];
    const float* W1b = (const float*)d_in[8],  *B1b = (const float*)d_in[9];
    const float* W2a = (const float*)d_in[10], *B2a = (const float*)d_in[11];
    const float* W2b = (const float*)d_in[12], *B2b = (const float*)d_in[13];
    const float* Wm1   = (const float*)d_in[14];
    const float* bm1   = (const float*)d_in[15];
    const float* gamma = (const float*)d_in[16];
    const float* beta  = (const float*)d_in[17];
    const float* Wm2   = (const float*)d_in[18];
    const float* bm2   = (const float*)d_in[19];
    float* out = (float*)d_out;

    const int E2 = (EE / 2 + 255) / 256;    // 3125 (2 edges/thread)
    const int NB = (NN + 255) / 256;        // 391
    const int SB = (NN * 8) / 256;          // 3125 (exact)
    const int GB = (NN + 63) / 64;          // 1563

    k_hist     <<<dim3(E2, 2), 256>>>(src0, dst0, src1, dst1);
    k_scan1    <<<dim3(SCAN_NB, 2), 256>>>();
    k_scanB    <<<dim3(NB, 2), 256>>>();
    k_scatter  <<<dim3(E2, 2), 256>>>(src0, dst0, src1, dst1);
    k_scalefeat<<<dim3(SB, 2), 256>>>(feat0, feat1);
    k_spmm     <<<dim3(SB, 2), 256>>>(0);
    k_gemm     <<<dim3(GB, 2), 128>>>(W1a, B1a, W2a, B2a, 1);   // layer 1: graph0->W1a, graph1->W2a
    k_spmm     <<<dim3(SB, 2), 256>>>(1);
    k_gemm     <<<dim3(GB, 2), 128>>>(W1b, B1b, W2b, B2b, 0);   // layer 2 + fused z-stats
    k_zy       <<<GB, 128>>>(Wm1, bm1, gamma, beta, out);       // + fused BN stats
    k_head     <<<GB, 192>>>(Wm2, bm2, out);
}